// round 2
// baseline (speedup 1.0000x reference)
#include <cuda_runtime.h>
#include <cuda_bf16.h>
#include <math_constants.h>

// Problem constants
#define Bc 4
#define Hc 16
#define Sc 2048
#define Dc 1024
#define DHc 64
#define Mrows (Bc*Sc)          // 8192

// Scratch (device globals; allocation via cudaMalloc is forbidden)
__device__ float g_q[Bc*Hc*Sc*DHc];   // [B,H,S,DH]
__device__ float g_k[Bc*Hc*Sc*DHc];
__device__ float g_v[Bc*Hc*Sc*DHc];
__device__ float g_o[Bc*Sc*Dc];       // [B,S,D] attention output

// ---------------------------------------------------------------------------
// NT GEMM: C[m,n] = sum_k A[m,k] * B[n,k] + bias[n]
// A: [M,K] row-major, B: [N,K] row-major. 128x128 block tile, BK=8,
// 8x8 per-thread microtile, 256 threads.
// mode 0: write C (row-major [M,N])
// mode 1: QKV scatter into g_q/g_k/g_v (layout [B,H,S,DH])
// ---------------------------------------------------------------------------
__global__ __launch_bounds__(256) void gemm_nt_kernel(
    const float* __restrict__ A, const float* __restrict__ B,
    const float* __restrict__ bias, float* __restrict__ C,
    int M, int N, int K, int mode)
{
    __shared__ float As[8][128];
    __shared__ float Bs[8][128];

    const int tid = threadIdx.x;
    const int m0 = blockIdx.y * 128;
    const int n0 = blockIdx.x * 128;
    const int tx = tid & 15;       // 0..15 -> n microtile
    const int ty = tid >> 4;       // 0..15 -> m microtile

    const int lrow = tid >> 1;         // 0..127
    const int lseg = (tid & 1) * 4;    // 0 or 4

    float acc[8][8];
#pragma unroll
    for (int i = 0; i < 8; i++)
#pragma unroll
        for (int j = 0; j < 8; j++) acc[i][j] = 0.f;

    const float* Aptr = A + (size_t)(m0 + lrow) * K + lseg;
    const float* Bptr = B + (size_t)(n0 + lrow) * K + lseg;

    for (int k0 = 0; k0 < K; k0 += 8) {
        float4 av = *(const float4*)(Aptr + k0);
        float4 bv = *(const float4*)(Bptr + k0);
        As[lseg + 0][lrow] = av.x;
        As[lseg + 1][lrow] = av.y;
        As[lseg + 2][lrow] = av.z;
        As[lseg + 3][lrow] = av.w;
        Bs[lseg + 0][lrow] = bv.x;
        Bs[lseg + 1][lrow] = bv.y;
        Bs[lseg + 2][lrow] = bv.z;
        Bs[lseg + 3][lrow] = bv.w;
        __syncthreads();

#pragma unroll
        for (int kk = 0; kk < 8; kk++) {
            float4 a0 = *(const float4*)&As[kk][ty * 8];
            float4 a1 = *(const float4*)&As[kk][ty * 8 + 4];
            float4 b0 = *(const float4*)&Bs[kk][tx * 8];
            float4 b1 = *(const float4*)&Bs[kk][tx * 8 + 4];
            float ra[8] = {a0.x, a0.y, a0.z, a0.w, a1.x, a1.y, a1.z, a1.w};
            float rb[8] = {b0.x, b0.y, b0.z, b0.w, b1.x, b1.y, b1.z, b1.w};
#pragma unroll
            for (int i = 0; i < 8; i++)
#pragma unroll
                for (int j = 0; j < 8; j++)
                    acc[i][j] += ra[i] * rb[j];
        }
        __syncthreads();
    }

    if (mode == 0) {
#pragma unroll
        for (int i = 0; i < 8; i++) {
            const int m = m0 + ty * 8 + i;
#pragma unroll
            for (int j = 0; j < 8; j++) {
                const int n = n0 + tx * 8 + j;
                C[(size_t)m * N + n] = acc[i][j] + bias[n];
            }
        }
    } else {
        // QKV scatter: n in [0,3072): h = n/192, which = (n%192)/64, dh = n%64
        //              m = b*2048 + s
#pragma unroll
        for (int i = 0; i < 8; i++) {
            const int m = m0 + ty * 8 + i;
            const int b = m >> 11;            // /2048
            const int s = m & 2047;
#pragma unroll
            for (int j = 0; j < 8; j++) {
                const int n = n0 + tx * 8 + j;
                const int h = n / 192;
                const int r = n - h * 192;
                const int which = r >> 6;
                const int dh = r & 63;
                const float v = acc[i][j] + bias[n];
                float* dst = (which == 0) ? g_q : (which == 1) ? g_k : g_v;
                dst[(((size_t)(b * Hc + h)) * Sc + s) * DHc + dh] = v;
            }
        }
    }
}

// ---------------------------------------------------------------------------
// Flash-style attention with ALiBi.
// Block: 128 threads, handles 32 queries of one (b,h). Streams K/V in chunks
// of 64 rows through smem. Thread microtile: 2 queries x 8 keys (scores) and
// 2 queries x 8 dims (PV). Online softmax, 8-lane shfl reductions.
// ---------------------------------------------------------------------------
__global__ __launch_bounds__(128) void attn_kernel(const float* __restrict__ alibi)
{
    __shared__ float Qs[32][65];
    __shared__ float Ks[64][65];
    __shared__ float Vs[64][65];
    __shared__ float Ps[32][65];   // holds alibi tile, then exp(p)

    const int tid = threadIdx.x;
    const int blk = blockIdx.x;
    const int qt  = blk & 63;        // 64 query tiles of 32
    const int bh  = blk >> 6;        // 0..63
    const int h   = bh & 15;
    const int b   = bh >> 4;
    const int q0  = qt * 32;

    const float* Qg = g_q + ((size_t)bh * Sc + q0) * DHc;
    const float* Kg = g_k + (size_t)bh * Sc * DHc;
    const float* Vg = g_v + (size_t)bh * Sc * DHc;
    const float* Ag = alibi + ((size_t)h * Sc + q0) * Sc;

    // Load Q tile (32x64, coalesced)
    for (int i = tid; i < 32 * 64; i += 128)
        Qs[i >> 6][i & 63] = Qg[i];

    const int qb = (tid >> 3) * 2;   // query pair base: 0,2,...,30
    const int kg = tid & 7;          // key-group / dim-group
    const int d0 = kg * 8;

    float m0 = -1e30f, m1 = -1e30f, l0 = 0.f, l1 = 0.f;
    float acc0[8], acc1[8];
#pragma unroll
    for (int i = 0; i < 8; i++) { acc0[i] = 0.f; acc1[i] = 0.f; }

    for (int c = 0; c < Sc; c += 64) {
        __syncthreads();   // protect smem reuse from previous iteration
        // Load K/V chunk (64x64 each, coalesced)
        for (int i = tid; i < 64 * 64; i += 128) {
            const int r = i >> 6, cc = i & 63;
            Ks[r][cc] = Kg[c * 64 + i];
            Vs[r][cc] = Vg[c * 64 + i];
        }
        // Stage alibi tile (32x64) into Ps, coalesced
        for (int i = tid; i < 32 * 64; i += 128)
            Ps[i >> 6][i & 63] = Ag[(size_t)(i >> 6) * Sc + c + (i & 63)];
        __syncthreads();

        // Scores: s[q][k] for my 2 queries x 8 keys
        float s0[8], s1[8];
#pragma unroll
        for (int kk = 0; kk < 8; kk++) { s0[kk] = 0.f; s1[kk] = 0.f; }
#pragma unroll 8
        for (int d = 0; d < 64; d++) {
            const float qv0 = Qs[qb][d];
            const float qv1 = Qs[qb + 1][d];
#pragma unroll
            for (int kk = 0; kk < 8; kk++) {
                const float kv = Ks[kg * 8 + kk][d];
                s0[kk] += qv0 * kv;
                s1[kk] += qv1 * kv;
            }
        }
        float mx0 = -1e30f, mx1 = -1e30f;
#pragma unroll
        for (int kk = 0; kk < 8; kk++) {
            s0[kk] = s0[kk] * 0.125f + Ps[qb][kg * 8 + kk];
            s1[kk] = s1[kk] * 0.125f + Ps[qb + 1][kg * 8 + kk];
            mx0 = fmaxf(mx0, s0[kk]);
            mx1 = fmaxf(mx1, s1[kk]);
        }
        // 8-lane group reductions (lanes kg=0..7 share a query pair)
#pragma unroll
        for (int off = 4; off; off >>= 1) {
            mx0 = fmaxf(mx0, __shfl_xor_sync(0xffffffffu, mx0, off));
            mx1 = fmaxf(mx1, __shfl_xor_sync(0xffffffffu, mx1, off));
        }
        const float mn0 = fmaxf(m0, mx0);
        const float mn1 = fmaxf(m1, mx1);
        float sum0 = 0.f, sum1 = 0.f;
#pragma unroll
        for (int kk = 0; kk < 8; kk++) {
            const float p0 = __expf(s0[kk] - mn0);
            const float p1 = __expf(s1[kk] - mn1);
            Ps[qb][kg * 8 + kk]     = p0;   // exclusive ownership: same slots we read
            Ps[qb + 1][kg * 8 + kk] = p1;
            sum0 += p0; sum1 += p1;
        }
#pragma unroll
        for (int off = 4; off; off >>= 1) {
            sum0 += __shfl_xor_sync(0xffffffffu, sum0, off);
            sum1 += __shfl_xor_sync(0xffffffffu, sum1, off);
        }
        const float c0 = __expf(m0 - mn0);
        const float c1 = __expf(m1 - mn1);
        l0 = l0 * c0 + sum0;
        l1 = l1 * c1 + sum1;
        m0 = mn0; m1 = mn1;
#pragma unroll
        for (int i = 0; i < 8; i++) { acc0[i] *= c0; acc1[i] *= c1; }
        __syncthreads();   // Ps(p) visible to all

        // PV: o[q][d0..d0+7] += sum_k p[q][k] * V[k][d]
#pragma unroll 8
        for (int k = 0; k < 64; k++) {
            const float p0 = Ps[qb][k];
            const float p1 = Ps[qb + 1][k];
#pragma unroll
            for (int i = 0; i < 8; i++) {
                const float vv = Vs[k][d0 + i];
                acc0[i] += p0 * vv;
                acc1[i] += p1 * vv;
            }
        }
    }

    const float inv0 = 1.f / l0;
    const float inv1 = 1.f / l1;
    float* dst0 = g_o + ((size_t)(b * Sc + q0 + qb)) * Dc + h * DHc + d0;
    float* dst1 = dst0 + Dc;
#pragma unroll
    for (int i = 0; i < 8; i++) {
        dst0[i] = acc0[i] * inv0;
        dst1[i] = acc1[i] * inv1;
    }
}

// ---------------------------------------------------------------------------
// kernel_launch
// Inputs (metadata order): x, alibi, w_qkv, b_qkv, w_o, b_o  (all fp32)
// ---------------------------------------------------------------------------
extern "C" void kernel_launch(void* const* d_in, const int* in_sizes, int n_in,
                              void* d_out, int out_size)
{
    const float* x     = (const float*)d_in[0];
    const float* alibi = (const float*)d_in[1];
    const float* w_qkv = (const float*)d_in[2];
    const float* b_qkv = (const float*)d_in[3];
    const float* w_o   = (const float*)d_in[4];
    const float* b_o   = (const float*)d_in[5];
    float* out = (float*)d_out;

    // 1) QKV projection: [8192,1024] x [3072,1024]^T -> scatter into q/k/v
    {
        dim3 grid(3 * Dc / 128, Mrows / 128);   // (24, 64)
        gemm_nt_kernel<<<grid, 256>>>(x, w_qkv, b_qkv, nullptr,
                                      Mrows, 3 * Dc, Dc, 1);
    }

    // 2) Attention (flash-style, streaming K/V)
    {
        dim3 grid(Bc * Hc * (Sc / 32));          // 4096
        attn_kernel<<<grid, 128>>>(alibi);
    }

    // 3) Output projection: [8192,1024] x [1024,1024]^T + b_o -> out
    {
        float* o_src;
        cudaGetSymbolAddress((void**)&o_src, g_o);
        dim3 grid(Dc / 128, Mrows / 128);        // (8, 64)
        gemm_nt_kernel<<<grid, 256>>>(o_src, w_o, b_o, out,
                                      Mrows, Dc, Dc, 0);
    }
}

// round 3
// speedup vs baseline: 1.0013x; 1.0013x over previous
#include <cuda_runtime.h>
#include <cuda_bf16.h>
#include <math_constants.h>

// Problem constants
#define Bc 4
#define Hc 16
#define Sc 2048
#define Dc 1024
#define DHc 64
#define Mrows (Bc*Sc)          // 8192

// Scratch (device globals; allocation via cudaMalloc is forbidden)
__device__ float g_q[Bc*Hc*Sc*DHc];   // [B,H,S,DH]
__device__ float g_k[Bc*Hc*Sc*DHc];
__device__ float g_v[Bc*Hc*Sc*DHc];
__device__ float g_o[Bc*Sc*Dc];       // [B,S,D] attention output

// ---------------------------------------------------------------------------
// NT GEMM: C[m,n] = sum_k A[m,k] * B[n,k] + bias[n]
// A: [M,K] row-major, B: [N,K] row-major. 128x128 block tile, BK=8,
// 8x8 per-thread microtile, 256 threads.
// mode 0: write C (row-major [M,N])
// mode 1: QKV scatter into g_q/g_k/g_v (layout [B,H,S,DH])
// ---------------------------------------------------------------------------
__global__ __launch_bounds__(256) void gemm_nt_kernel(
    const float* __restrict__ A, const float* __restrict__ B,
    const float* __restrict__ bias, float* __restrict__ C,
    int M, int N, int K, int mode)
{
    __shared__ float As[8][128];
    __shared__ float Bs[8][128];

    const int tid = threadIdx.x;
    const int m0 = blockIdx.y * 128;
    const int n0 = blockIdx.x * 128;
    const int tx = tid & 15;       // 0..15 -> n microtile
    const int ty = tid >> 4;       // 0..15 -> m microtile

    const int lrow = tid >> 1;         // 0..127
    const int lseg = (tid & 1) * 4;    // 0 or 4

    float acc[8][8];
#pragma unroll
    for (int i = 0; i < 8; i++)
#pragma unroll
        for (int j = 0; j < 8; j++) acc[i][j] = 0.f;

    const float* Aptr = A + (size_t)(m0 + lrow) * K + lseg;
    const float* Bptr = B + (size_t)(n0 + lrow) * K + lseg;

    for (int k0 = 0; k0 < K; k0 += 8) {
        float4 av = *(const float4*)(Aptr + k0);
        float4 bv = *(const float4*)(Bptr + k0);
        As[lseg + 0][lrow] = av.x;
        As[lseg + 1][lrow] = av.y;
        As[lseg + 2][lrow] = av.z;
        As[lseg + 3][lrow] = av.w;
        Bs[lseg + 0][lrow] = bv.x;
        Bs[lseg + 1][lrow] = bv.y;
        Bs[lseg + 2][lrow] = bv.z;
        Bs[lseg + 3][lrow] = bv.w;
        __syncthreads();

#pragma unroll
        for (int kk = 0; kk < 8; kk++) {
            float4 a0 = *(const float4*)&As[kk][ty * 8];
            float4 a1 = *(const float4*)&As[kk][ty * 8 + 4];
            float4 b0 = *(const float4*)&Bs[kk][tx * 8];
            float4 b1 = *(const float4*)&Bs[kk][tx * 8 + 4];
            float ra[8] = {a0.x, a0.y, a0.z, a0.w, a1.x, a1.y, a1.z, a1.w};
            float rb[8] = {b0.x, b0.y, b0.z, b0.w, b1.x, b1.y, b1.z, b1.w};
#pragma unroll
            for (int i = 0; i < 8; i++)
#pragma unroll
                for (int j = 0; j < 8; j++)
                    acc[i][j] += ra[i] * rb[j];
        }
        __syncthreads();
    }

    if (mode == 0) {
#pragma unroll
        for (int i = 0; i < 8; i++) {
            const int m = m0 + ty * 8 + i;
#pragma unroll
            for (int j = 0; j < 8; j++) {
                const int n = n0 + tx * 8 + j;
                C[(size_t)m * N + n] = acc[i][j] + bias[n];
            }
        }
    } else {
        // QKV scatter: n in [0,3072): h = n/192, which = (n%192)/64, dh = n%64
        //              m = b*2048 + s
#pragma unroll
        for (int i = 0; i < 8; i++) {
            const int m = m0 + ty * 8 + i;
            const int b = m >> 11;            // /2048
            const int s = m & 2047;
#pragma unroll
            for (int j = 0; j < 8; j++) {
                const int n = n0 + tx * 8 + j;
                const int h = n / 192;
                const int r = n - h * 192;
                const int which = r >> 6;
                const int dh = r & 63;
                const float v = acc[i][j] + bias[n];
                float* dst = (which == 0) ? g_q : (which == 1) ? g_k : g_v;
                dst[(((size_t)(b * Hc + h)) * Sc + s) * DHc + dh] = v;
            }
        }
    }
}

// ---------------------------------------------------------------------------
// Flash-style attention with ALiBi.
// Block: 128 threads, handles 32 queries of one (b,h). Streams K/V in chunks
// of 64 rows through smem. Thread microtile: 2 queries x 8 keys (scores) and
// 2 queries x 8 dims (PV). Online softmax, 8-lane shfl reductions.
// ---------------------------------------------------------------------------
__global__ __launch_bounds__(128) void attn_kernel(const float* __restrict__ alibi)
{
    __shared__ float Qs[32][65];
    __shared__ float Ks[64][65];
    __shared__ float Vs[64][65];
    __shared__ float Ps[32][65];   // holds alibi tile, then exp(p)

    const int tid = threadIdx.x;
    const int blk = blockIdx.x;
    const int qt  = blk & 63;        // 64 query tiles of 32
    const int bh  = blk >> 6;        // 0..63
    const int h   = bh & 15;
    const int b   = bh >> 4;
    const int q0  = qt * 32;

    const float* Qg = g_q + ((size_t)bh * Sc + q0) * DHc;
    const float* Kg = g_k + (size_t)bh * Sc * DHc;
    const float* Vg = g_v + (size_t)bh * Sc * DHc;
    const float* Ag = alibi + ((size_t)h * Sc + q0) * Sc;

    // Load Q tile (32x64, coalesced)
    for (int i = tid; i < 32 * 64; i += 128)
        Qs[i >> 6][i & 63] = Qg[i];

    const int qb = (tid >> 3) * 2;   // query pair base: 0,2,...,30
    const int kg = tid & 7;          // key-group / dim-group
    const int d0 = kg * 8;

    float m0 = -1e30f, m1 = -1e30f, l0 = 0.f, l1 = 0.f;
    float acc0[8], acc1[8];
#pragma unroll
    for (int i = 0; i < 8; i++) { acc0[i] = 0.f; acc1[i] = 0.f; }

    for (int c = 0; c < Sc; c += 64) {
        __syncthreads();   // protect smem reuse from previous iteration
        // Load K/V chunk (64x64 each, coalesced)
        for (int i = tid; i < 64 * 64; i += 128) {
            const int r = i >> 6, cc = i & 63;
            Ks[r][cc] = Kg[c * 64 + i];
            Vs[r][cc] = Vg[c * 64 + i];
        }
        // Stage alibi tile (32x64) into Ps, coalesced
        for (int i = tid; i < 32 * 64; i += 128)
            Ps[i >> 6][i & 63] = Ag[(size_t)(i >> 6) * Sc + c + (i & 63)];
        __syncthreads();

        // Scores: s[q][k] for my 2 queries x 8 keys
        float s0[8], s1[8];
#pragma unroll
        for (int kk = 0; kk < 8; kk++) { s0[kk] = 0.f; s1[kk] = 0.f; }
#pragma unroll 8
        for (int d = 0; d < 64; d++) {
            const float qv0 = Qs[qb][d];
            const float qv1 = Qs[qb + 1][d];
#pragma unroll
            for (int kk = 0; kk < 8; kk++) {
                const float kv = Ks[kg * 8 + kk][d];
                s0[kk] += qv0 * kv;
                s1[kk] += qv1 * kv;
            }
        }
        float mx0 = -1e30f, mx1 = -1e30f;
#pragma unroll
        for (int kk = 0; kk < 8; kk++) {
            s0[kk] = s0[kk] * 0.125f + Ps[qb][kg * 8 + kk];
            s1[kk] = s1[kk] * 0.125f + Ps[qb + 1][kg * 8 + kk];
            mx0 = fmaxf(mx0, s0[kk]);
            mx1 = fmaxf(mx1, s1[kk]);
        }
        // 8-lane group reductions (lanes kg=0..7 share a query pair)
#pragma unroll
        for (int off = 4; off; off >>= 1) {
            mx0 = fmaxf(mx0, __shfl_xor_sync(0xffffffffu, mx0, off));
            mx1 = fmaxf(mx1, __shfl_xor_sync(0xffffffffu, mx1, off));
        }
        const float mn0 = fmaxf(m0, mx0);
        const float mn1 = fmaxf(m1, mx1);
        float sum0 = 0.f, sum1 = 0.f;
#pragma unroll
        for (int kk = 0; kk < 8; kk++) {
            const float p0 = __expf(s0[kk] - mn0);
            const float p1 = __expf(s1[kk] - mn1);
            Ps[qb][kg * 8 + kk]     = p0;   // exclusive ownership: same slots we read
            Ps[qb + 1][kg * 8 + kk] = p1;
            sum0 += p0; sum1 += p1;
        }
#pragma unroll
        for (int off = 4; off; off >>= 1) {
            sum0 += __shfl_xor_sync(0xffffffffu, sum0, off);
            sum1 += __shfl_xor_sync(0xffffffffu, sum1, off);
        }
        const float c0 = __expf(m0 - mn0);
        const float c1 = __expf(m1 - mn1);
        l0 = l0 * c0 + sum0;
        l1 = l1 * c1 + sum1;
        m0 = mn0; m1 = mn1;
#pragma unroll
        for (int i = 0; i < 8; i++) { acc0[i] *= c0; acc1[i] *= c1; }
        __syncthreads();   // Ps(p) visible to all

        // PV: o[q][d0..d0+7] += sum_k p[q][k] * V[k][d]
#pragma unroll 8
        for (int k = 0; k < 64; k++) {
            const float p0 = Ps[qb][k];
            const float p1 = Ps[qb + 1][k];
#pragma unroll
            for (int i = 0; i < 8; i++) {
                const float vv = Vs[k][d0 + i];
                acc0[i] += p0 * vv;
                acc1[i] += p1 * vv;
            }
        }
    }

    const float inv0 = 1.f / l0;
    const float inv1 = 1.f / l1;
    float* dst0 = g_o + ((size_t)(b * Sc + q0 + qb)) * Dc + h * DHc + d0;
    float* dst1 = dst0 + Dc;
#pragma unroll
    for (int i = 0; i < 8; i++) {
        dst0[i] = acc0[i] * inv0;
        dst1[i] = acc1[i] * inv1;
    }
}

// ---------------------------------------------------------------------------
// kernel_launch
// Inputs (metadata order): x, alibi, w_qkv, b_qkv, w_o, b_o  (all fp32)
// ---------------------------------------------------------------------------
extern "C" void kernel_launch(void* const* d_in, const int* in_sizes, int n_in,
                              void* d_out, int out_size)
{
    const float* x     = (const float*)d_in[0];
    const float* alibi = (const float*)d_in[1];
    const float* w_qkv = (const float*)d_in[2];
    const float* b_qkv = (const float*)d_in[3];
    const float* w_o   = (const float*)d_in[4];
    const float* b_o   = (const float*)d_in[5];
    float* out = (float*)d_out;

    // 1) QKV projection: [8192,1024] x [3072,1024]^T -> scatter into q/k/v
    {
        dim3 grid(3 * Dc / 128, Mrows / 128);   // (24, 64)
        gemm_nt_kernel<<<grid, 256>>>(x, w_qkv, b_qkv, nullptr,
                                      Mrows, 3 * Dc, Dc, 1);
    }

    // 2) Attention (flash-style, streaming K/V)
    {
        dim3 grid(Bc * Hc * (Sc / 32));          // 4096
        attn_kernel<<<grid, 128>>>(alibi);
    }

    // 3) Output projection: [8192,1024] x [1024,1024]^T + b_o -> out
    {
        float* o_src;
        cudaGetSymbolAddress((void**)&o_src, g_o);
        dim3 grid(Dc / 128, Mrows / 128);        // (8, 64)
        gemm_nt_kernel<<<grid, 256>>>(o_src, w_o, b_o, out,
                                      Mrows, Dc, Dc, 0);
    }
}

// round 5
// speedup vs baseline: 1.2357x; 1.2341x over previous
#include <cuda_runtime.h>
#include <cuda_bf16.h>
#include <cstdint>

// Problem constants
#define Bc 4
#define Hc 16
#define Sc 2048
#define Dc 1024
#define DHc 64
#define Mrows (Bc*Sc)          // 8192

// Scratch (device globals; allocation is forbidden)
__device__ float g_q[Bc*Hc*Sc*DHc];   // [B,H,S,DH]
__device__ float g_k[Bc*Hc*Sc*DHc];
__device__ float g_v[Bc*Hc*Sc*DHc];
__device__ float g_o[Bc*Sc*Dc];       // [B,S,D] attention output

// ===========================================================================
// HMMA helpers (mma.sync path — tcgen05 is unavailable: harness compiles via
// virtual arch compute_103, which lacks the sm_103a feature suffix)
// ===========================================================================
__device__ __forceinline__ uint32_t smem_u32(const void* p) {
    uint32_t a;
    asm("{ .reg .u64 t; cvta.to.shared.u64 t, %1; cvt.u32.u64 %0, t; }"
        : "=r"(a) : "l"(p));
    return a;
}

__device__ __forceinline__ void ldsm_x4(uint32_t* r, uint32_t addr) {
    asm volatile("ldmatrix.sync.aligned.m8n8.x4.shared.b16 {%0,%1,%2,%3}, [%4];"
        : "=r"(r[0]), "=r"(r[1]), "=r"(r[2]), "=r"(r[3]) : "r"(addr));
}
__device__ __forceinline__ void ldsm_x2(uint32_t* r, uint32_t addr) {
    asm volatile("ldmatrix.sync.aligned.m8n8.x2.shared.b16 {%0,%1}, [%2];"
        : "=r"(r[0]), "=r"(r[1]) : "r"(addr));
}
__device__ __forceinline__ void mma16816(float* c, const uint32_t* a, const uint32_t* b) {
    asm volatile("mma.sync.aligned.m16n8k16.row.col.f32.bf16.bf16.f32 "
        "{%0,%1,%2,%3}, {%4,%5,%6,%7}, {%8,%9}, {%0,%1,%2,%3};"
        : "+f"(c[0]), "+f"(c[1]), "+f"(c[2]), "+f"(c[3])
        : "r"(a[0]), "r"(a[1]), "r"(a[2]), "r"(a[3]), "r"(b[0]), "r"(b[1]));
}

// ===========================================================================
// Split-bf16 NT GEMM on HMMA: C[m,n] = sum_k A[m,k]*B[n,k] + bias[n]
// 3-term split: a = hi(trunc bf16) + lo(rn bf16); D += AhBh + AhBl + AlBh.
// Block 128x128, BK=32 (fp32), 8 warps (2M x 4N -> 64x32 warp tile),
// 2-stage smem double buffer + register prefetch.
// smem tiles: bf16, row stride 40 b16 (80B) -> conflict-free ldmatrix.
// mode 0: row-major C.  mode 1: QKV scatter into g_q/g_k/g_v.
// ===========================================================================
#define RS 80                   // row stride bytes
#define TILE_BYTES (128*RS)     // 10240
#define STG_BYTES  (4*TILE_BYTES)  // Ahi,Alo,Bhi,Blo = 40960
#define GSMEM_TOTAL (2*STG_BYTES)  // 81920

__global__ __launch_bounds__(256, 1)
void gemm_hmma(const float* __restrict__ A, const float* __restrict__ Bw,
               const float* __restrict__ bias, float* __restrict__ C,
               int M, int N, int K, int mode)
{
    extern __shared__ char smem[];
    const uint32_t sb = smem_u32(smem);
    const int tid  = threadIdx.x;
    const int wid  = tid >> 5;
    const int lane = tid & 31;
    const int m0 = blockIdx.y * 128;
    const int n0 = blockIdx.x * 128;
    const int warpM = wid & 1;         // 0..1
    const int warpN = wid >> 1;        // 0..3

    float acc[4][4][4];
#pragma unroll
    for (int i = 0; i < 4; i++)
#pragma unroll
        for (int j = 0; j < 4; j++)
#pragma unroll
            for (int q = 0; q < 4; q++) acc[i][j][q] = 0.f;

    const int nch = K >> 5;            // K chunks of 32

    // per-thread load coords: 1024 float4 per tile, 4 per thread
    const int lrow = tid >> 1;                    // reused below differently
    (void)lrow;

    float4 pa[4], pb[4];

    auto load_chunk = [&](int c) {
#pragma unroll
        for (int it = 0; it < 4; ++it) {
            const int idx = it * 256 + tid;       // 0..1023
            const int row = idx >> 3;             // 0..127
            const int c4  = idx & 7;              // 0..7 (float4 col)
            pa[it] = *(const float4*)(A + (size_t)(m0 + row) * K + c * 32 + c4 * 4);
            pb[it] = *(const float4*)(Bw + (size_t)(n0 + row) * K + c * 32 + c4 * 4);
        }
    };

    auto split_store = [&](uint32_t hiT, uint32_t loT, const float4& v, uint32_t off) {
        uint32_t bx = __float_as_uint(v.x), by = __float_as_uint(v.y),
                 bz = __float_as_uint(v.z), bw = __float_as_uint(v.w);
        uint32_t hi01 = __byte_perm(bx, by, 0x7632);
        uint32_t hi23 = __byte_perm(bz, bw, 0x7632);
        float lx = v.x - __uint_as_float(bx & 0xFFFF0000u);
        float ly = v.y - __uint_as_float(by & 0xFFFF0000u);
        float lz = v.z - __uint_as_float(bz & 0xFFFF0000u);
        float lw = v.w - __uint_as_float(bw & 0xFFFF0000u);
        __nv_bfloat162 l01 = __floats2bfloat162_rn(lx, ly);
        __nv_bfloat162 l23 = __floats2bfloat162_rn(lz, lw);
        asm volatile("st.shared.v2.b32 [%0], {%1, %2};"
                     :: "r"(hiT + off), "r"(hi01), "r"(hi23));
        asm volatile("st.shared.v2.b32 [%0], {%1, %2};"
                     :: "r"(loT + off), "r"(*(uint32_t*)&l01), "r"(*(uint32_t*)&l23));
    };

    auto store_chunk = [&](int s) {
        const uint32_t st  = sb + s * STG_BYTES;
        const uint32_t sAh = st, sAl = st + TILE_BYTES,
                       sBh = st + 2*TILE_BYTES, sBl = st + 3*TILE_BYTES;
#pragma unroll
        for (int it = 0; it < 4; ++it) {
            const int idx = it * 256 + tid;
            const int row = idx >> 3;
            const int c4  = idx & 7;
            const uint32_t off = row * RS + c4 * 8;
            split_store(sAh, sAl, pa[it], off);
            split_store(sBh, sBl, pb[it], off);
        }
    };

    load_chunk(0);
    store_chunk(0);
    __syncthreads();

    for (int c = 0; c < nch; ++c) {
        if (c + 1 < nch) load_chunk(c + 1);

        const uint32_t st  = sb + (c & 1) * STG_BYTES;
        const uint32_t sAh = st, sAl = st + TILE_BYTES,
                       sBh = st + 2*TILE_BYTES, sBl = st + 3*TILE_BYTES;

#pragma unroll
        for (int ks = 0; ks < 2; ++ks) {
            uint32_t ah[4][4], al[4][4], bh[4][2], bl[4][2];
            const uint32_t aRowOff = (warpM * 64 + (lane & 15)) * RS + ks * 32 + (lane >> 4) * 16;
            const uint32_t bRowOff = (warpN * 32 + (lane & 7)) * RS + ks * 32 + ((lane >> 3) & 1) * 16;
#pragma unroll
            for (int mi = 0; mi < 4; ++mi) {
                ldsm_x4(ah[mi], sAh + aRowOff + mi * 16 * RS);
                ldsm_x4(al[mi], sAl + aRowOff + mi * 16 * RS);
            }
#pragma unroll
            for (int ni = 0; ni < 4; ++ni) {
                ldsm_x2(bh[ni], sBh + bRowOff + ni * 8 * RS);
                ldsm_x2(bl[ni], sBl + bRowOff + ni * 8 * RS);
            }
#pragma unroll
            for (int mi = 0; mi < 4; ++mi)
#pragma unroll
                for (int ni = 0; ni < 4; ++ni) {
                    mma16816(acc[mi][ni], ah[mi], bh[ni]);
                    mma16816(acc[mi][ni], ah[mi], bl[ni]);
                    mma16816(acc[mi][ni], al[mi], bh[ni]);
                }
        }

        if (c + 1 < nch) store_chunk((c + 1) & 1);
        __syncthreads();
    }

    // Epilogue: per-warp 64x32 tile; thread holds 2x2 per (mi,ni) frag.
#pragma unroll
    for (int mi = 0; mi < 4; ++mi) {
#pragma unroll
        for (int ni = 0; ni < 4; ++ni) {
            const int gm = m0 + warpM * 64 + mi * 16 + (lane >> 2);
            const int gn = n0 + warpN * 32 + ni * 8 + (lane & 3) * 2;
            const float b0 = __ldg(bias + gn);
            const float b1 = __ldg(bias + gn + 1);
            float v00 = acc[mi][ni][0] + b0, v01 = acc[mi][ni][1] + b1;
            float v10 = acc[mi][ni][2] + b0, v11 = acc[mi][ni][3] + b1;
            if (mode == 0) {
                *(float2*)(C + (size_t)gm * N + gn)       = make_float2(v00, v01);
                *(float2*)(C + (size_t)(gm + 8) * N + gn) = make_float2(v10, v11);
            } else {
                const int h   = gn / 192;
                const int rmd = gn - h * 192;
                const int which = rmd >> 6;
                const int dh = rmd & 63;
                float* base = (which == 0) ? g_q : (which == 1) ? g_k : g_v;
                const int b_0 = gm >> 11, s_0 = gm & 2047;
                const int b_1 = (gm + 8) >> 11, s_1 = (gm + 8) & 2047;
                *(float2*)(base + (((size_t)(b_0 * Hc + h)) * Sc + s_0) * DHc + dh) = make_float2(v00, v01);
                *(float2*)(base + (((size_t)(b_1 * Hc + h)) * Sc + s_1) * DHc + dh) = make_float2(v10, v11);
            }
        }
    }
}

// ===========================================================================
// Flash-style attention with ALiBi (SIMT, unchanged)
// ===========================================================================
__global__ __launch_bounds__(128) void attn_kernel(const float* __restrict__ alibi)
{
    __shared__ float Qs[32][65];
    __shared__ float Ks[64][65];
    __shared__ float Vs[64][65];
    __shared__ float Ps[32][65];

    const int tid = threadIdx.x;
    const int blk = blockIdx.x;
    const int qt  = blk & 63;
    const int bh  = blk >> 6;
    const int h   = bh & 15;
    const int b   = bh >> 4;
    const int q0  = qt * 32;

    const float* Qg = g_q + ((size_t)bh * Sc + q0) * DHc;
    const float* Kg = g_k + (size_t)bh * Sc * DHc;
    const float* Vg = g_v + (size_t)bh * Sc * DHc;
    const float* Ag = alibi + ((size_t)h * Sc + q0) * Sc;

    for (int i = tid; i < 32 * 64; i += 128)
        Qs[i >> 6][i & 63] = Qg[i];

    const int qb = (tid >> 3) * 2;
    const int kg = tid & 7;
    const int d0 = kg * 8;

    float m0 = -1e30f, m1 = -1e30f, l0 = 0.f, l1 = 0.f;
    float acc0[8], acc1[8];
#pragma unroll
    for (int i = 0; i < 8; i++) { acc0[i] = 0.f; acc1[i] = 0.f; }

    for (int c = 0; c < Sc; c += 64) {
        __syncthreads();
        for (int i = tid; i < 64 * 64; i += 128) {
            const int r = i >> 6, cc = i & 63;
            Ks[r][cc] = Kg[c * 64 + i];
            Vs[r][cc] = Vg[c * 64 + i];
        }
        for (int i = tid; i < 32 * 64; i += 128)
            Ps[i >> 6][i & 63] = Ag[(size_t)(i >> 6) * Sc + c + (i & 63)];
        __syncthreads();

        float s0[8], s1[8];
#pragma unroll
        for (int kk = 0; kk < 8; kk++) { s0[kk] = 0.f; s1[kk] = 0.f; }
#pragma unroll 8
        for (int d = 0; d < 64; d++) {
            const float qv0 = Qs[qb][d];
            const float qv1 = Qs[qb + 1][d];
#pragma unroll
            for (int kk = 0; kk < 8; kk++) {
                const float kv = Ks[kg * 8 + kk][d];
                s0[kk] += qv0 * kv;
                s1[kk] += qv1 * kv;
            }
        }
        float mx0 = -1e30f, mx1 = -1e30f;
#pragma unroll
        for (int kk = 0; kk < 8; kk++) {
            s0[kk] = s0[kk] * 0.125f + Ps[qb][kg * 8 + kk];
            s1[kk] = s1[kk] * 0.125f + Ps[qb + 1][kg * 8 + kk];
            mx0 = fmaxf(mx0, s0[kk]);
            mx1 = fmaxf(mx1, s1[kk]);
        }
#pragma unroll
        for (int off = 4; off; off >>= 1) {
            mx0 = fmaxf(mx0, __shfl_xor_sync(0xffffffffu, mx0, off));
            mx1 = fmaxf(mx1, __shfl_xor_sync(0xffffffffu, mx1, off));
        }
        const float mn0 = fmaxf(m0, mx0);
        const float mn1 = fmaxf(m1, mx1);
        float sum0 = 0.f, sum1 = 0.f;
#pragma unroll
        for (int kk = 0; kk < 8; kk++) {
            const float p0 = __expf(s0[kk] - mn0);
            const float p1 = __expf(s1[kk] - mn1);
            Ps[qb][kg * 8 + kk]     = p0;
            Ps[qb + 1][kg * 8 + kk] = p1;
            sum0 += p0; sum1 += p1;
        }
#pragma unroll
        for (int off = 4; off; off >>= 1) {
            sum0 += __shfl_xor_sync(0xffffffffu, sum0, off);
            sum1 += __shfl_xor_sync(0xffffffffu, sum1, off);
        }
        const float c0 = __expf(m0 - mn0);
        const float c1 = __expf(m1 - mn1);
        l0 = l0 * c0 + sum0;
        l1 = l1 * c1 + sum1;
        m0 = mn0; m1 = mn1;
#pragma unroll
        for (int i = 0; i < 8; i++) { acc0[i] *= c0; acc1[i] *= c1; }
        __syncthreads();

#pragma unroll 8
        for (int k = 0; k < 64; k++) {
            const float p0 = Ps[qb][k];
            const float p1 = Ps[qb + 1][k];
#pragma unroll
            for (int i = 0; i < 8; i++) {
                const float vv = Vs[k][d0 + i];
                acc0[i] += p0 * vv;
                acc1[i] += p1 * vv;
            }
        }
    }

    const float inv0 = 1.f / l0;
    const float inv1 = 1.f / l1;
    float* dst0 = g_o + ((size_t)(b * Sc + q0 + qb)) * Dc + h * DHc + d0;
    float* dst1 = dst0 + Dc;
#pragma unroll
    for (int i = 0; i < 8; i++) {
        dst0[i] = acc0[i] * inv0;
        dst1[i] = acc1[i] * inv1;
    }
}

// ===========================================================================
// kernel_launch: x, alibi, w_qkv, b_qkv, w_o, b_o (all fp32)
// ===========================================================================
extern "C" void kernel_launch(void* const* d_in, const int* in_sizes, int n_in,
                              void* d_out, int out_size)
{
    const float* x     = (const float*)d_in[0];
    const float* alibi = (const float*)d_in[1];
    const float* w_qkv = (const float*)d_in[2];
    const float* b_qkv = (const float*)d_in[3];
    const float* w_o   = (const float*)d_in[4];
    const float* b_o   = (const float*)d_in[5];
    float* out = (float*)d_out;

    cudaFuncSetAttribute(gemm_hmma, cudaFuncAttributeMaxDynamicSharedMemorySize, GSMEM_TOTAL);

    // 1) QKV projection: [8192,1024] x [3072,1024]^T -> q/k/v scatter
    {
        dim3 grid(3 * Dc / 128, Mrows / 128);   // (24, 64)
        gemm_hmma<<<grid, 256, GSMEM_TOTAL>>>(x, w_qkv, b_qkv, nullptr,
                                              Mrows, 3 * Dc, Dc, 1);
    }

    // 2) Attention (flash-style SIMT)
    {
        dim3 grid(Bc * Hc * (Sc / 32));          // 4096
        attn_kernel<<<grid, 128>>>(alibi);
    }

    // 3) Output projection: [8192,1024] x [1024,1024]^T + b_o -> out
    {
        float* o_src;
        cudaGetSymbolAddress((void**)&o_src, g_o);
        dim3 grid(Dc / 128, Mrows / 128);        // (8, 64)
        gemm_hmma<<<grid, 256, GSMEM_TOTAL>>>(o_src, w_o, b_o, out,
                                              Mrows, Dc, Dc, 0);
    }
}

// round 6
// speedup vs baseline: 1.2381x; 1.0019x over previous
#include <cuda_runtime.h>
#include <cuda_bf16.h>
#include <cstdint>

// Problem constants
#define Bc 4
#define Hc 16
#define Sc 2048
#define Dc 1024
#define DHc 64
#define Mrows (Bc*Sc)          // 8192

// Scratch (device globals; allocation is forbidden)
__device__ float g_q[Bc*Hc*Sc*DHc];   // [B,H,S,DH]
__device__ float g_k[Bc*Hc*Sc*DHc];
__device__ float g_v[Bc*Hc*Sc*DHc];
__device__ float g_o[Bc*Sc*Dc];       // [B,S,D] attention output

// ===========================================================================
// HMMA helpers (mma.sync path — tcgen05 is unavailable: harness compiles via
// virtual arch compute_103, which lacks the sm_103a feature suffix)
// ===========================================================================
__device__ __forceinline__ uint32_t smem_u32(const void* p) {
    uint32_t a;
    asm("{ .reg .u64 t; cvta.to.shared.u64 t, %1; cvt.u32.u64 %0, t; }"
        : "=r"(a) : "l"(p));
    return a;
}

__device__ __forceinline__ void ldsm_x4(uint32_t* r, uint32_t addr) {
    asm volatile("ldmatrix.sync.aligned.m8n8.x4.shared.b16 {%0,%1,%2,%3}, [%4];"
        : "=r"(r[0]), "=r"(r[1]), "=r"(r[2]), "=r"(r[3]) : "r"(addr));
}
__device__ __forceinline__ void ldsm_x2(uint32_t* r, uint32_t addr) {
    asm volatile("ldmatrix.sync.aligned.m8n8.x2.shared.b16 {%0,%1}, [%2];"
        : "=r"(r[0]), "=r"(r[1]) : "r"(addr));
}
__device__ __forceinline__ void mma16816(float* c, const uint32_t* a, const uint32_t* b) {
    asm volatile("mma.sync.aligned.m16n8k16.row.col.f32.bf16.bf16.f32 "
        "{%0,%1,%2,%3}, {%4,%5,%6,%7}, {%8,%9}, {%0,%1,%2,%3};"
        : "+f"(c[0]), "+f"(c[1]), "+f"(c[2]), "+f"(c[3])
        : "r"(a[0]), "r"(a[1]), "r"(a[2]), "r"(a[3]), "r"(b[0]), "r"(b[1]));
}

// ===========================================================================
// Split-bf16 NT GEMM on HMMA: C[m,n] = sum_k A[m,k]*B[n,k] + bias[n]
// 3-term split: a = hi(trunc bf16) + lo(rn bf16); D += AhBh + AhBl + AlBh.
// Block 128x128, BK=32 (fp32), 8 warps (2M x 4N -> 64x32 warp tile),
// 2-stage smem double buffer + register prefetch.
// smem tiles: bf16, row stride 40 b16 (80B) -> conflict-free ldmatrix.
// mode 0: row-major C.  mode 1: QKV scatter into g_q/g_k/g_v.
// ===========================================================================
#define RS 80                   // row stride bytes
#define TILE_BYTES (128*RS)     // 10240
#define STG_BYTES  (4*TILE_BYTES)  // Ahi,Alo,Bhi,Blo = 40960
#define GSMEM_TOTAL (2*STG_BYTES)  // 81920

__global__ __launch_bounds__(256, 1)
void gemm_hmma(const float* __restrict__ A, const float* __restrict__ Bw,
               const float* __restrict__ bias, float* __restrict__ C,
               int M, int N, int K, int mode)
{
    extern __shared__ char smem[];
    const uint32_t sb = smem_u32(smem);
    const int tid  = threadIdx.x;
    const int wid  = tid >> 5;
    const int lane = tid & 31;
    const int m0 = blockIdx.y * 128;
    const int n0 = blockIdx.x * 128;
    const int warpM = wid & 1;         // 0..1
    const int warpN = wid >> 1;        // 0..3

    float acc[4][4][4];
#pragma unroll
    for (int i = 0; i < 4; i++)
#pragma unroll
        for (int j = 0; j < 4; j++)
#pragma unroll
            for (int q = 0; q < 4; q++) acc[i][j][q] = 0.f;

    const int nch = K >> 5;            // K chunks of 32

    // per-thread load coords: 1024 float4 per tile, 4 per thread
    const int lrow = tid >> 1;                    // reused below differently
    (void)lrow;

    float4 pa[4], pb[4];

    auto load_chunk = [&](int c) {
#pragma unroll
        for (int it = 0; it < 4; ++it) {
            const int idx = it * 256 + tid;       // 0..1023
            const int row = idx >> 3;             // 0..127
            const int c4  = idx & 7;              // 0..7 (float4 col)
            pa[it] = *(const float4*)(A + (size_t)(m0 + row) * K + c * 32 + c4 * 4);
            pb[it] = *(const float4*)(Bw + (size_t)(n0 + row) * K + c * 32 + c4 * 4);
        }
    };

    auto split_store = [&](uint32_t hiT, uint32_t loT, const float4& v, uint32_t off) {
        uint32_t bx = __float_as_uint(v.x), by = __float_as_uint(v.y),
                 bz = __float_as_uint(v.z), bw = __float_as_uint(v.w);
        uint32_t hi01 = __byte_perm(bx, by, 0x7632);
        uint32_t hi23 = __byte_perm(bz, bw, 0x7632);
        float lx = v.x - __uint_as_float(bx & 0xFFFF0000u);
        float ly = v.y - __uint_as_float(by & 0xFFFF0000u);
        float lz = v.z - __uint_as_float(bz & 0xFFFF0000u);
        float lw = v.w - __uint_as_float(bw & 0xFFFF0000u);
        __nv_bfloat162 l01 = __floats2bfloat162_rn(lx, ly);
        __nv_bfloat162 l23 = __floats2bfloat162_rn(lz, lw);
        asm volatile("st.shared.v2.b32 [%0], {%1, %2};"
                     :: "r"(hiT + off), "r"(hi01), "r"(hi23));
        asm volatile("st.shared.v2.b32 [%0], {%1, %2};"
                     :: "r"(loT + off), "r"(*(uint32_t*)&l01), "r"(*(uint32_t*)&l23));
    };

    auto store_chunk = [&](int s) {
        const uint32_t st  = sb + s * STG_BYTES;
        const uint32_t sAh = st, sAl = st + TILE_BYTES,
                       sBh = st + 2*TILE_BYTES, sBl = st + 3*TILE_BYTES;
#pragma unroll
        for (int it = 0; it < 4; ++it) {
            const int idx = it * 256 + tid;
            const int row = idx >> 3;
            const int c4  = idx & 7;
            const uint32_t off = row * RS + c4 * 8;
            split_store(sAh, sAl, pa[it], off);
            split_store(sBh, sBl, pb[it], off);
        }
    };

    load_chunk(0);
    store_chunk(0);
    __syncthreads();

    for (int c = 0; c < nch; ++c) {
        if (c + 1 < nch) load_chunk(c + 1);

        const uint32_t st  = sb + (c & 1) * STG_BYTES;
        const uint32_t sAh = st, sAl = st + TILE_BYTES,
                       sBh = st + 2*TILE_BYTES, sBl = st + 3*TILE_BYTES;

#pragma unroll
        for (int ks = 0; ks < 2; ++ks) {
            uint32_t ah[4][4], al[4][4], bh[4][2], bl[4][2];
            const uint32_t aRowOff = (warpM * 64 + (lane & 15)) * RS + ks * 32 + (lane >> 4) * 16;
            const uint32_t bRowOff = (warpN * 32 + (lane & 7)) * RS + ks * 32 + ((lane >> 3) & 1) * 16;
#pragma unroll
            for (int mi = 0; mi < 4; ++mi) {
                ldsm_x4(ah[mi], sAh + aRowOff + mi * 16 * RS);
                ldsm_x4(al[mi], sAl + aRowOff + mi * 16 * RS);
            }
#pragma unroll
            for (int ni = 0; ni < 4; ++ni) {
                ldsm_x2(bh[ni], sBh + bRowOff + ni * 8 * RS);
                ldsm_x2(bl[ni], sBl + bRowOff + ni * 8 * RS);
            }
#pragma unroll
            for (int mi = 0; mi < 4; ++mi)
#pragma unroll
                for (int ni = 0; ni < 4; ++ni) {
                    mma16816(acc[mi][ni], ah[mi], bh[ni]);
                    mma16816(acc[mi][ni], ah[mi], bl[ni]);
                    mma16816(acc[mi][ni], al[mi], bh[ni]);
                }
        }

        if (c + 1 < nch) store_chunk((c + 1) & 1);
        __syncthreads();
    }

    // Epilogue: per-warp 64x32 tile; thread holds 2x2 per (mi,ni) frag.
#pragma unroll
    for (int mi = 0; mi < 4; ++mi) {
#pragma unroll
        for (int ni = 0; ni < 4; ++ni) {
            const int gm = m0 + warpM * 64 + mi * 16 + (lane >> 2);
            const int gn = n0 + warpN * 32 + ni * 8 + (lane & 3) * 2;
            const float b0 = __ldg(bias + gn);
            const float b1 = __ldg(bias + gn + 1);
            float v00 = acc[mi][ni][0] + b0, v01 = acc[mi][ni][1] + b1;
            float v10 = acc[mi][ni][2] + b0, v11 = acc[mi][ni][3] + b1;
            if (mode == 0) {
                *(float2*)(C + (size_t)gm * N + gn)       = make_float2(v00, v01);
                *(float2*)(C + (size_t)(gm + 8) * N + gn) = make_float2(v10, v11);
            } else {
                const int h   = gn / 192;
                const int rmd = gn - h * 192;
                const int which = rmd >> 6;
                const int dh = rmd & 63;
                float* base = (which == 0) ? g_q : (which == 1) ? g_k : g_v;
                const int b_0 = gm >> 11, s_0 = gm & 2047;
                const int b_1 = (gm + 8) >> 11, s_1 = (gm + 8) & 2047;
                *(float2*)(base + (((size_t)(b_0 * Hc + h)) * Sc + s_0) * DHc + dh) = make_float2(v00, v01);
                *(float2*)(base + (((size_t)(b_1 * Hc + h)) * Sc + s_1) * DHc + dh) = make_float2(v10, v11);
            }
        }
    }
}

// ===========================================================================
// Flash-style attention with ALiBi (SIMT, unchanged)
// ===========================================================================
__global__ __launch_bounds__(128) void attn_kernel(const float* __restrict__ alibi)
{
    __shared__ float Qs[32][65];
    __shared__ float Ks[64][65];
    __shared__ float Vs[64][65];
    __shared__ float Ps[32][65];

    const int tid = threadIdx.x;
    const int blk = blockIdx.x;
    const int qt  = blk & 63;
    const int bh  = blk >> 6;
    const int h   = bh & 15;
    const int b   = bh >> 4;
    const int q0  = qt * 32;

    const float* Qg = g_q + ((size_t)bh * Sc + q0) * DHc;
    const float* Kg = g_k + (size_t)bh * Sc * DHc;
    const float* Vg = g_v + (size_t)bh * Sc * DHc;
    const float* Ag = alibi + ((size_t)h * Sc + q0) * Sc;

    for (int i = tid; i < 32 * 64; i += 128)
        Qs[i >> 6][i & 63] = Qg[i];

    const int qb = (tid >> 3) * 2;
    const int kg = tid & 7;
    const int d0 = kg * 8;

    float m0 = -1e30f, m1 = -1e30f, l0 = 0.f, l1 = 0.f;
    float acc0[8], acc1[8];
#pragma unroll
    for (int i = 0; i < 8; i++) { acc0[i] = 0.f; acc1[i] = 0.f; }

    for (int c = 0; c < Sc; c += 64) {
        __syncthreads();
        for (int i = tid; i < 64 * 64; i += 128) {
            const int r = i >> 6, cc = i & 63;
            Ks[r][cc] = Kg[c * 64 + i];
            Vs[r][cc] = Vg[c * 64 + i];
        }
        for (int i = tid; i < 32 * 64; i += 128)
            Ps[i >> 6][i & 63] = Ag[(size_t)(i >> 6) * Sc + c + (i & 63)];
        __syncthreads();

        float s0[8], s1[8];
#pragma unroll
        for (int kk = 0; kk < 8; kk++) { s0[kk] = 0.f; s1[kk] = 0.f; }
#pragma unroll 8
        for (int d = 0; d < 64; d++) {
            const float qv0 = Qs[qb][d];
            const float qv1 = Qs[qb + 1][d];
#pragma unroll
            for (int kk = 0; kk < 8; kk++) {
                const float kv = Ks[kg * 8 + kk][d];
                s0[kk] += qv0 * kv;
                s1[kk] += qv1 * kv;
            }
        }
        float mx0 = -1e30f, mx1 = -1e30f;
#pragma unroll
        for (int kk = 0; kk < 8; kk++) {
            s0[kk] = s0[kk] * 0.125f + Ps[qb][kg * 8 + kk];
            s1[kk] = s1[kk] * 0.125f + Ps[qb + 1][kg * 8 + kk];
            mx0 = fmaxf(mx0, s0[kk]);
            mx1 = fmaxf(mx1, s1[kk]);
        }
#pragma unroll
        for (int off = 4; off; off >>= 1) {
            mx0 = fmaxf(mx0, __shfl_xor_sync(0xffffffffu, mx0, off));
            mx1 = fmaxf(mx1, __shfl_xor_sync(0xffffffffu, mx1, off));
        }
        const float mn0 = fmaxf(m0, mx0);
        const float mn1 = fmaxf(m1, mx1);
        float sum0 = 0.f, sum1 = 0.f;
#pragma unroll
        for (int kk = 0; kk < 8; kk++) {
            const float p0 = __expf(s0[kk] - mn0);
            const float p1 = __expf(s1[kk] - mn1);
            Ps[qb][kg * 8 + kk]     = p0;
            Ps[qb + 1][kg * 8 + kk] = p1;
            sum0 += p0; sum1 += p1;
        }
#pragma unroll
        for (int off = 4; off; off >>= 1) {
            sum0 += __shfl_xor_sync(0xffffffffu, sum0, off);
            sum1 += __shfl_xor_sync(0xffffffffu, sum1, off);
        }
        const float c0 = __expf(m0 - mn0);
        const float c1 = __expf(m1 - mn1);
        l0 = l0 * c0 + sum0;
        l1 = l1 * c1 + sum1;
        m0 = mn0; m1 = mn1;
#pragma unroll
        for (int i = 0; i < 8; i++) { acc0[i] *= c0; acc1[i] *= c1; }
        __syncthreads();

#pragma unroll 8
        for (int k = 0; k < 64; k++) {
            const float p0 = Ps[qb][k];
            const float p1 = Ps[qb + 1][k];
#pragma unroll
            for (int i = 0; i < 8; i++) {
                const float vv = Vs[k][d0 + i];
                acc0[i] += p0 * vv;
                acc1[i] += p1 * vv;
            }
        }
    }

    const float inv0 = 1.f / l0;
    const float inv1 = 1.f / l1;
    float* dst0 = g_o + ((size_t)(b * Sc + q0 + qb)) * Dc + h * DHc + d0;
    float* dst1 = dst0 + Dc;
#pragma unroll
    for (int i = 0; i < 8; i++) {
        dst0[i] = acc0[i] * inv0;
        dst1[i] = acc1[i] * inv1;
    }
}

// ===========================================================================
// kernel_launch: x, alibi, w_qkv, b_qkv, w_o, b_o (all fp32)
// ===========================================================================
extern "C" void kernel_launch(void* const* d_in, const int* in_sizes, int n_in,
                              void* d_out, int out_size)
{
    const float* x     = (const float*)d_in[0];
    const float* alibi = (const float*)d_in[1];
    const float* w_qkv = (const float*)d_in[2];
    const float* b_qkv = (const float*)d_in[3];
    const float* w_o   = (const float*)d_in[4];
    const float* b_o   = (const float*)d_in[5];
    float* out = (float*)d_out;

    cudaFuncSetAttribute(gemm_hmma, cudaFuncAttributeMaxDynamicSharedMemorySize, GSMEM_TOTAL);

    // 1) QKV projection: [8192,1024] x [3072,1024]^T -> q/k/v scatter
    {
        dim3 grid(3 * Dc / 128, Mrows / 128);   // (24, 64)
        gemm_hmma<<<grid, 256, GSMEM_TOTAL>>>(x, w_qkv, b_qkv, nullptr,
                                              Mrows, 3 * Dc, Dc, 1);
    }

    // 2) Attention (flash-style SIMT)
    {
        dim3 grid(Bc * Hc * (Sc / 32));          // 4096
        attn_kernel<<<grid, 128>>>(alibi);
    }

    // 3) Output projection: [8192,1024] x [1024,1024]^T + b_o -> out
    {
        float* o_src;
        cudaGetSymbolAddress((void**)&o_src, g_o);
        dim3 grid(Dc / 128, Mrows / 128);        // (8, 64)
        gemm_hmma<<<grid, 256, GSMEM_TOTAL>>>(o_src, w_o, b_o, out,
                                              Mrows, Dc, Dc, 0);
    }
}

// round 7
// speedup vs baseline: 1.2388x; 1.0006x over previous
#include <cuda_runtime.h>
#include <cuda_bf16.h>
#include <cstdint>

// Problem constants
#define Bc 4
#define Hc 16
#define Sc 2048
#define Dc 1024
#define DHc 64
#define Mrows (Bc*Sc)          // 8192

// Scratch (device globals; allocation is forbidden)
__device__ float g_q[Bc*Hc*Sc*DHc];   // [B,H,S,DH]
__device__ float g_k[Bc*Hc*Sc*DHc];
__device__ float g_v[Bc*Hc*Sc*DHc];
__device__ float g_o[Bc*Sc*Dc];       // [B,S,D] attention output

// ===========================================================================
// HMMA helpers (mma.sync path — tcgen05 is unavailable: harness compiles via
// virtual arch compute_103, which lacks the sm_103a feature suffix)
// ===========================================================================
__device__ __forceinline__ uint32_t smem_u32(const void* p) {
    uint32_t a;
    asm("{ .reg .u64 t; cvta.to.shared.u64 t, %1; cvt.u32.u64 %0, t; }"
        : "=r"(a) : "l"(p));
    return a;
}

__device__ __forceinline__ void ldsm_x4(uint32_t* r, uint32_t addr) {
    asm volatile("ldmatrix.sync.aligned.m8n8.x4.shared.b16 {%0,%1,%2,%3}, [%4];"
        : "=r"(r[0]), "=r"(r[1]), "=r"(r[2]), "=r"(r[3]) : "r"(addr));
}
__device__ __forceinline__ void ldsm_x2(uint32_t* r, uint32_t addr) {
    asm volatile("ldmatrix.sync.aligned.m8n8.x2.shared.b16 {%0,%1}, [%2];"
        : "=r"(r[0]), "=r"(r[1]) : "r"(addr));
}
__device__ __forceinline__ void mma16816(float* c, const uint32_t* a, const uint32_t* b) {
    asm volatile("mma.sync.aligned.m16n8k16.row.col.f32.bf16.bf16.f32 "
        "{%0,%1,%2,%3}, {%4,%5,%6,%7}, {%8,%9}, {%0,%1,%2,%3};"
        : "+f"(c[0]), "+f"(c[1]), "+f"(c[2]), "+f"(c[3])
        : "r"(a[0]), "r"(a[1]), "r"(a[2]), "r"(a[3]), "r"(b[0]), "r"(b[1]));
}

// ===========================================================================
// Split-bf16 NT GEMM on HMMA: C[m,n] = sum_k A[m,k]*B[n,k] + bias[n]
// 3-term split: a = hi(trunc bf16) + lo(rn bf16); D += AhBh + AhBl + AlBh.
// Block 128x128, BK=32 (fp32), 8 warps (2M x 4N -> 64x32 warp tile),
// 2-stage smem double buffer + register prefetch.
// smem tiles: bf16, row stride 40 b16 (80B) -> conflict-free ldmatrix.
// mode 0: row-major C.  mode 1: QKV scatter into g_q/g_k/g_v.
// ===========================================================================
#define RS 80                   // row stride bytes
#define TILE_BYTES (128*RS)     // 10240
#define STG_BYTES  (4*TILE_BYTES)  // Ahi,Alo,Bhi,Blo = 40960
#define GSMEM_TOTAL (2*STG_BYTES)  // 81920

__global__ __launch_bounds__(256, 1)
void gemm_hmma(const float* __restrict__ A, const float* __restrict__ Bw,
               const float* __restrict__ bias, float* __restrict__ C,
               int M, int N, int K, int mode)
{
    extern __shared__ char smem[];
    const uint32_t sb = smem_u32(smem);
    const int tid  = threadIdx.x;
    const int wid  = tid >> 5;
    const int lane = tid & 31;
    const int m0 = blockIdx.y * 128;
    const int n0 = blockIdx.x * 128;
    const int warpM = wid & 1;         // 0..1
    const int warpN = wid >> 1;        // 0..3

    float acc[4][4][4];
#pragma unroll
    for (int i = 0; i < 4; i++)
#pragma unroll
        for (int j = 0; j < 4; j++)
#pragma unroll
            for (int q = 0; q < 4; q++) acc[i][j][q] = 0.f;

    const int nch = K >> 5;            // K chunks of 32

    // per-thread load coords: 1024 float4 per tile, 4 per thread
    const int lrow = tid >> 1;                    // reused below differently
    (void)lrow;

    float4 pa[4], pb[4];

    auto load_chunk = [&](int c) {
#pragma unroll
        for (int it = 0; it < 4; ++it) {
            const int idx = it * 256 + tid;       // 0..1023
            const int row = idx >> 3;             // 0..127
            const int c4  = idx & 7;              // 0..7 (float4 col)
            pa[it] = *(const float4*)(A + (size_t)(m0 + row) * K + c * 32 + c4 * 4);
            pb[it] = *(const float4*)(Bw + (size_t)(n0 + row) * K + c * 32 + c4 * 4);
        }
    };

    auto split_store = [&](uint32_t hiT, uint32_t loT, const float4& v, uint32_t off) {
        uint32_t bx = __float_as_uint(v.x), by = __float_as_uint(v.y),
                 bz = __float_as_uint(v.z), bw = __float_as_uint(v.w);
        uint32_t hi01 = __byte_perm(bx, by, 0x7632);
        uint32_t hi23 = __byte_perm(bz, bw, 0x7632);
        float lx = v.x - __uint_as_float(bx & 0xFFFF0000u);
        float ly = v.y - __uint_as_float(by & 0xFFFF0000u);
        float lz = v.z - __uint_as_float(bz & 0xFFFF0000u);
        float lw = v.w - __uint_as_float(bw & 0xFFFF0000u);
        __nv_bfloat162 l01 = __floats2bfloat162_rn(lx, ly);
        __nv_bfloat162 l23 = __floats2bfloat162_rn(lz, lw);
        asm volatile("st.shared.v2.b32 [%0], {%1, %2};"
                     :: "r"(hiT + off), "r"(hi01), "r"(hi23));
        asm volatile("st.shared.v2.b32 [%0], {%1, %2};"
                     :: "r"(loT + off), "r"(*(uint32_t*)&l01), "r"(*(uint32_t*)&l23));
    };

    auto store_chunk = [&](int s) {
        const uint32_t st  = sb + s * STG_BYTES;
        const uint32_t sAh = st, sAl = st + TILE_BYTES,
                       sBh = st + 2*TILE_BYTES, sBl = st + 3*TILE_BYTES;
#pragma unroll
        for (int it = 0; it < 4; ++it) {
            const int idx = it * 256 + tid;
            const int row = idx >> 3;
            const int c4  = idx & 7;
            const uint32_t off = row * RS + c4 * 8;
            split_store(sAh, sAl, pa[it], off);
            split_store(sBh, sBl, pb[it], off);
        }
    };

    load_chunk(0);
    store_chunk(0);
    __syncthreads();

    for (int c = 0; c < nch; ++c) {
        if (c + 1 < nch) load_chunk(c + 1);

        const uint32_t st  = sb + (c & 1) * STG_BYTES;
        const uint32_t sAh = st, sAl = st + TILE_BYTES,
                       sBh = st + 2*TILE_BYTES, sBl = st + 3*TILE_BYTES;

#pragma unroll
        for (int ks = 0; ks < 2; ++ks) {
            uint32_t ah[4][4], al[4][4], bh[4][2], bl[4][2];
            const uint32_t aRowOff = (warpM * 64 + (lane & 15)) * RS + ks * 32 + (lane >> 4) * 16;
            const uint32_t bRowOff = (warpN * 32 + (lane & 7)) * RS + ks * 32 + ((lane >> 3) & 1) * 16;
#pragma unroll
            for (int mi = 0; mi < 4; ++mi) {
                ldsm_x4(ah[mi], sAh + aRowOff + mi * 16 * RS);
                ldsm_x4(al[mi], sAl + aRowOff + mi * 16 * RS);
            }
#pragma unroll
            for (int ni = 0; ni < 4; ++ni) {
                ldsm_x2(bh[ni], sBh + bRowOff + ni * 8 * RS);
                ldsm_x2(bl[ni], sBl + bRowOff + ni * 8 * RS);
            }
#pragma unroll
            for (int mi = 0; mi < 4; ++mi)
#pragma unroll
                for (int ni = 0; ni < 4; ++ni) {
                    mma16816(acc[mi][ni], ah[mi], bh[ni]);
                    mma16816(acc[mi][ni], ah[mi], bl[ni]);
                    mma16816(acc[mi][ni], al[mi], bh[ni]);
                }
        }

        if (c + 1 < nch) store_chunk((c + 1) & 1);
        __syncthreads();
    }

    // Epilogue: per-warp 64x32 tile; thread holds 2x2 per (mi,ni) frag.
#pragma unroll
    for (int mi = 0; mi < 4; ++mi) {
#pragma unroll
        for (int ni = 0; ni < 4; ++ni) {
            const int gm = m0 + warpM * 64 + mi * 16 + (lane >> 2);
            const int gn = n0 + warpN * 32 + ni * 8 + (lane & 3) * 2;
            const float b0 = __ldg(bias + gn);
            const float b1 = __ldg(bias + gn + 1);
            float v00 = acc[mi][ni][0] + b0, v01 = acc[mi][ni][1] + b1;
            float v10 = acc[mi][ni][2] + b0, v11 = acc[mi][ni][3] + b1;
            if (mode == 0) {
                *(float2*)(C + (size_t)gm * N + gn)       = make_float2(v00, v01);
                *(float2*)(C + (size_t)(gm + 8) * N + gn) = make_float2(v10, v11);
            } else {
                const int h   = gn / 192;
                const int rmd = gn - h * 192;
                const int which = rmd >> 6;
                const int dh = rmd & 63;
                float* base = (which == 0) ? g_q : (which == 1) ? g_k : g_v;
                const int b_0 = gm >> 11, s_0 = gm & 2047;
                const int b_1 = (gm + 8) >> 11, s_1 = (gm + 8) & 2047;
                *(float2*)(base + (((size_t)(b_0 * Hc + h)) * Sc + s_0) * DHc + dh) = make_float2(v00, v01);
                *(float2*)(base + (((size_t)(b_1 * Hc + h)) * Sc + s_1) * DHc + dh) = make_float2(v10, v11);
            }
        }
    }
}

// ===========================================================================
// Flash-style attention with ALiBi (SIMT, unchanged)
// ===========================================================================
__global__ __launch_bounds__(128) void attn_kernel(const float* __restrict__ alibi)
{
    __shared__ float Qs[32][65];
    __shared__ float Ks[64][65];
    __shared__ float Vs[64][65];
    __shared__ float Ps[32][65];

    const int tid = threadIdx.x;
    const int blk = blockIdx.x;
    const int qt  = blk & 63;
    const int bh  = blk >> 6;
    const int h   = bh & 15;
    const int b   = bh >> 4;
    const int q0  = qt * 32;

    const float* Qg = g_q + ((size_t)bh * Sc + q0) * DHc;
    const float* Kg = g_k + (size_t)bh * Sc * DHc;
    const float* Vg = g_v + (size_t)bh * Sc * DHc;
    const float* Ag = alibi + ((size_t)h * Sc + q0) * Sc;

    for (int i = tid; i < 32 * 64; i += 128)
        Qs[i >> 6][i & 63] = Qg[i];

    const int qb = (tid >> 3) * 2;
    const int kg = tid & 7;
    const int d0 = kg * 8;

    float m0 = -1e30f, m1 = -1e30f, l0 = 0.f, l1 = 0.f;
    float acc0[8], acc1[8];
#pragma unroll
    for (int i = 0; i < 8; i++) { acc0[i] = 0.f; acc1[i] = 0.f; }

    for (int c = 0; c < Sc; c += 64) {
        __syncthreads();
        for (int i = tid; i < 64 * 64; i += 128) {
            const int r = i >> 6, cc = i & 63;
            Ks[r][cc] = Kg[c * 64 + i];
            Vs[r][cc] = Vg[c * 64 + i];
        }
        for (int i = tid; i < 32 * 64; i += 128)
            Ps[i >> 6][i & 63] = Ag[(size_t)(i >> 6) * Sc + c + (i & 63)];
        __syncthreads();

        float s0[8], s1[8];
#pragma unroll
        for (int kk = 0; kk < 8; kk++) { s0[kk] = 0.f; s1[kk] = 0.f; }
#pragma unroll 8
        for (int d = 0; d < 64; d++) {
            const float qv0 = Qs[qb][d];
            const float qv1 = Qs[qb + 1][d];
#pragma unroll
            for (int kk = 0; kk < 8; kk++) {
                const float kv = Ks[kg * 8 + kk][d];
                s0[kk] += qv0 * kv;
                s1[kk] += qv1 * kv;
            }
        }
        float mx0 = -1e30f, mx1 = -1e30f;
#pragma unroll
        for (int kk = 0; kk < 8; kk++) {
            s0[kk] = s0[kk] * 0.125f + Ps[qb][kg * 8 + kk];
            s1[kk] = s1[kk] * 0.125f + Ps[qb + 1][kg * 8 + kk];
            mx0 = fmaxf(mx0, s0[kk]);
            mx1 = fmaxf(mx1, s1[kk]);
        }
#pragma unroll
        for (int off = 4; off; off >>= 1) {
            mx0 = fmaxf(mx0, __shfl_xor_sync(0xffffffffu, mx0, off));
            mx1 = fmaxf(mx1, __shfl_xor_sync(0xffffffffu, mx1, off));
        }
        const float mn0 = fmaxf(m0, mx0);
        const float mn1 = fmaxf(m1, mx1);
        float sum0 = 0.f, sum1 = 0.f;
#pragma unroll
        for (int kk = 0; kk < 8; kk++) {
            const float p0 = __expf(s0[kk] - mn0);
            const float p1 = __expf(s1[kk] - mn1);
            Ps[qb][kg * 8 + kk]     = p0;
            Ps[qb + 1][kg * 8 + kk] = p1;
            sum0 += p0; sum1 += p1;
        }
#pragma unroll
        for (int off = 4; off; off >>= 1) {
            sum0 += __shfl_xor_sync(0xffffffffu, sum0, off);
            sum1 += __shfl_xor_sync(0xffffffffu, sum1, off);
        }
        const float c0 = __expf(m0 - mn0);
        const float c1 = __expf(m1 - mn1);
        l0 = l0 * c0 + sum0;
        l1 = l1 * c1 + sum1;
        m0 = mn0; m1 = mn1;
#pragma unroll
        for (int i = 0; i < 8; i++) { acc0[i] *= c0; acc1[i] *= c1; }
        __syncthreads();

#pragma unroll 8
        for (int k = 0; k < 64; k++) {
            const float p0 = Ps[qb][k];
            const float p1 = Ps[qb + 1][k];
#pragma unroll
            for (int i = 0; i < 8; i++) {
                const float vv = Vs[k][d0 + i];
                acc0[i] += p0 * vv;
                acc1[i] += p1 * vv;
            }
        }
    }

    const float inv0 = 1.f / l0;
    const float inv1 = 1.f / l1;
    float* dst0 = g_o + ((size_t)(b * Sc + q0 + qb)) * Dc + h * DHc + d0;
    float* dst1 = dst0 + Dc;
#pragma unroll
    for (int i = 0; i < 8; i++) {
        dst0[i] = acc0[i] * inv0;
        dst1[i] = acc1[i] * inv1;
    }
}

// ===========================================================================
// kernel_launch: x, alibi, w_qkv, b_qkv, w_o, b_o (all fp32)
// ===========================================================================
extern "C" void kernel_launch(void* const* d_in, const int* in_sizes, int n_in,
                              void* d_out, int out_size)
{
    const float* x     = (const float*)d_in[0];
    const float* alibi = (const float*)d_in[1];
    const float* w_qkv = (const float*)d_in[2];
    const float* b_qkv = (const float*)d_in[3];
    const float* w_o   = (const float*)d_in[4];
    const float* b_o   = (const float*)d_in[5];
    float* out = (float*)d_out;

    cudaFuncSetAttribute(gemm_hmma, cudaFuncAttributeMaxDynamicSharedMemorySize, GSMEM_TOTAL);

    // 1) QKV projection: [8192,1024] x [3072,1024]^T -> q/k/v scatter
    {
        dim3 grid(3 * Dc / 128, Mrows / 128);   // (24, 64)
        gemm_hmma<<<grid, 256, GSMEM_TOTAL>>>(x, w_qkv, b_qkv, nullptr,
                                              Mrows, 3 * Dc, Dc, 1);
    }

    // 2) Attention (flash-style SIMT)
    {
        dim3 grid(Bc * Hc * (Sc / 32));          // 4096
        attn_kernel<<<grid, 128>>>(alibi);
    }

    // 3) Output projection: [8192,1024] x [1024,1024]^T + b_o -> out
    {
        float* o_src;
        cudaGetSymbolAddress((void**)&o_src, g_o);
        dim3 grid(Dc / 128, Mrows / 128);        // (8, 64)
        gemm_hmma<<<grid, 256, GSMEM_TOTAL>>>(o_src, w_o, b_o, out,
                                              Mrows, Dc, Dc, 0);
    }
}